// round 11
// baseline (speedup 1.0000x reference)
#include <cuda_runtime.h>
#include <cuda_fp16.h>
#include <math.h>

#define NN 50000
#define NE 800000
#define DD 128
#define NG 3
#define NT128 ((NN + 127) / 128)   // 391
#define ZPH 136                    // padded row pitch in halves
#define NNP (NN + 4)               // padded so each d_start row is 16B-aligned

// ---------------- scratch ----------------------------------------------------
__device__ int           d_deg[NG][NN];       // zeroed statically; reset by gather (after last read)
__device__ int           d_start[NG][NNP];    // CSR offsets; [NN] holds NE
__device__ int           d_cursor[NG][NN];
__device__ int           d_srcs[NG][NE];
__device__ unsigned char d_y8[NG][NN * DD];   // fp8 e4m3 of 64*dinv[n]*x[n]
__device__ __half        d_z[NG][NN * DD];    // aggregated features (fp16)
__device__ __half        d_wt[NG][DD * DD];   // W transposed fp16
__device__ float         d_gsum[NG][DD];      // zeroed statically; reset by finalize

// ---------------- fp8 helpers -------------------------------------------------
__device__ __forceinline__ unsigned short f32x2_to_e4m3x2(float lo, float hi) {
    unsigned short r;
    asm("cvt.rn.satfinite.e4m3x2.f32 %0, %1, %2;" : "=h"(r) : "f"(hi), "f"(lo));
    return r;
}
__device__ __forceinline__ __half2 e4m3x2_to_h2(unsigned short u) {
    unsigned r;
    asm("cvt.rn.f16x2.e4m3x2 %0, %1;" : "=r"(r) : "h"(u));
    return *(__half2*)&r;
}

// ---------------- hist --------------------------------------------------------
__global__ void hist_kernel(const int* __restrict__ e1,
                            const int* __restrict__ e2,
                            const int* __restrict__ e3) {
    int g = blockIdx.y;
    const int* ei = (g == 0) ? e1 : ((g == 1) ? e2 : e3);
    const int4* dst4 = (const int4*)(ei + NE);
    int stride = gridDim.x * blockDim.x;
    for (int i = blockIdx.x * blockDim.x + threadIdx.x; i < NE / 4; i += stride) {
        int4 d = dst4[i];
        atomicAdd(&d_deg[g][d.x], 1);
        atomicAdd(&d_deg[g][d.y], 1);
        atomicAdd(&d_deg[g][d.z], 1);
        atomicAdd(&d_deg[g][d.w], 1);
    }
}

// ---------------- single-kernel scan: 1 block/graph, pure integer work --------
// Produces d_start, d_cursor. No MUFU, no deg reset (gather does that).
#define SCH 52          // nodes per thread (13 int4), 1024*52 = 53248 >= NN
__global__ void __launch_bounds__(1024, 1) scan_kernel() {
    int g = blockIdx.x;
    int t = threadIdx.x;
    int base = t * SCH;

    int4 v4[13];
    int s = 0;
    const int4* deg4 = (const int4*)d_deg[g];
    #pragma unroll
    for (int j = 0; j < 13; j++) {
        int idx = base + j * 4;
        if (idx < NN) {
            v4[j] = deg4[(base >> 2) + j];
            s += v4[j].x + v4[j].y + v4[j].z + v4[j].w;
        } else {
            v4[j] = make_int4(0, 0, 0, 0);
        }
    }

    // block-wide exclusive prefix of per-thread sums
    int lane = t & 31, wid = t >> 5;
    int incl = s;
    #pragma unroll
    for (int o = 1; o < 32; o <<= 1) {
        int y = __shfl_up_sync(0xffffffffu, incl, o);
        if (lane >= o) incl += y;
    }
    __shared__ int ws[32];
    if (lane == 31) ws[wid] = incl;
    __syncthreads();
    if (wid == 0) {
        int w = ws[lane];
        int wi = w;
        #pragma unroll
        for (int o = 1; o < 32; o <<= 1) {
            int y = __shfl_up_sync(0xffffffffu, wi, o);
            if (lane >= o) wi += y;
        }
        ws[lane] = wi - w;     // exclusive
    }
    __syncthreads();
    int run = ws[wid] + (incl - s);

    int4* start4 = (int4*)d_start[g];     // row is 16B-aligned (NNP % 4 == 0)
    int4* cur4   = (int4*)d_cursor[g];
    #pragma unroll
    for (int j = 0; j < 13; j++) {
        int idx = base + j * 4;
        if (idx < NN) {
            int4 v = v4[j];
            int4 st;
            st.x = run;
            st.y = st.x + v.x;
            st.z = st.y + v.y;
            st.w = st.z + v.z;
            run = st.w + v.w;
            int vi = (base >> 2) + j;
            start4[vi] = st;
            cur4[vi]   = st;
        }
    }
    if (t == 0) d_start[g][NN] = NE;
}

// ---------------- merged fill + convert (x->fp8) + W transpose ----------------
// grid (772, NG): bx<256 fill, 256<=bx<768 convert, bx>=768 W transpose
__global__ void fill_convert_kernel(const int* __restrict__ e1,
                                    const int* __restrict__ e2,
                                    const int* __restrict__ e3,
                                    const float* __restrict__ x1,
                                    const float* __restrict__ x2,
                                    const float* __restrict__ x3,
                                    const float* __restrict__ W1,
                                    const float* __restrict__ W2,
                                    const float* __restrict__ W3) {
    int g = blockIdx.y;
    int t = threadIdx.x;
    int bx = blockIdx.x;

    if (bx < 256) {
        // ---- fill CSR ----
        const int* ei = (g == 0) ? e1 : ((g == 1) ? e2 : e3);
        const int4* src4 = (const int4*)ei;
        const int4* dst4 = (const int4*)(ei + NE);
        int stride = 256 * 256;
        int* srcs = d_srcs[g];
        int* cur  = d_cursor[g];
        for (int i = bx * 256 + t; i < NE / 4; i += stride) {
            int4 sv = src4[i];
            int4 dv = dst4[i];
            srcs[atomicAdd(&cur[dv.x], 1)] = sv.x;
            srcs[atomicAdd(&cur[dv.y], 1)] = sv.y;
            srcs[atomicAdd(&cur[dv.z], 1)] = sv.z;
            srcs[atomicAdd(&cur[dv.w], 1)] = sv.w;
        }
    } else if (bx < 768) {
        // ---- convert x -> fp8 y8; scale computed inline from deg ----
        const float4* x4 = (const float4*)((g == 0) ? x1 : ((g == 1) ? x2 : x3));
        const int* deg = d_deg[g];
        uint4* y4 = (uint4*)d_y8[g];
        int stride = 512 * 256;
        for (int i = (bx - 256) * 256 + t; i < NN * 8; i += stride) {
            int n = i >> 3;
            int c = i & 7;
            float sc = 64.f * rsqrtf((float)(deg[n] + 1));
            const float4* xp = x4 + n * 32 + c * 4;
            float4 v0 = xp[0], v1 = xp[1], v2 = xp[2], v3 = xp[3];
            unsigned short s0 = f32x2_to_e4m3x2(sc * v0.x, sc * v0.y);
            unsigned short s1 = f32x2_to_e4m3x2(sc * v0.z, sc * v0.w);
            unsigned short s2 = f32x2_to_e4m3x2(sc * v1.x, sc * v1.y);
            unsigned short s3 = f32x2_to_e4m3x2(sc * v1.z, sc * v1.w);
            unsigned short s4 = f32x2_to_e4m3x2(sc * v2.x, sc * v2.y);
            unsigned short s5 = f32x2_to_e4m3x2(sc * v2.z, sc * v2.w);
            unsigned short s6 = f32x2_to_e4m3x2(sc * v3.x, sc * v3.y);
            unsigned short s7 = f32x2_to_e4m3x2(sc * v3.z, sc * v3.w);
            uint4 o;
            o.x = (unsigned)s0 | ((unsigned)s1 << 16);
            o.y = (unsigned)s2 | ((unsigned)s3 << 16);
            o.z = (unsigned)s4 | ((unsigned)s5 << 16);
            o.w = (unsigned)s6 | ((unsigned)s7 << 16);
            y4[i] = o;
        }
    } else {
        // ---- W transpose -> fp16 ----
        const float* W = (g == 0) ? W1 : ((g == 1) ? W2 : W3);
        __half* wt = d_wt[g];
        int gid = (bx - 768) * 256 + t;   // 0..1023
        int j = gid >> 3;
        int k0 = (gid & 7) * 16;
        #pragma unroll
        for (int kk = 0; kk < 16; kk++)
            wt[j * DD + k0 + kk] = __float2half(W[(k0 + kk) * DD + j]);
    }
}

// ---------------- gather (fp8 reads, fp16 accum) ------------------------------
// Also: lane 0 resets d_deg[n] to 0 after its last read (replay invariant).
__global__ void gather_kernel() {
    int g = blockIdx.y;
    const uint4* ybase = (const uint4*)d_y8[g];   // row = 8 uint4
    int warp = (blockIdx.x * blockDim.x + threadIdx.x) >> 5;
    int lane = threadIdx.x & 31;
    if (warp >= NN) return;
    int n = warp;
    int ep  = lane >> 3;        // edge slot 0..3
    int off = lane & 7;         // 16B chunk within row
    int s = d_start[g][n];
    int e = d_start[g][n + 1];
    int degn = d_deg[g][n];
    if (lane == 0) d_deg[g][n] = 0;     // reset for next invocation
    const int* srcs = d_srcs[g];

    __half2 zero2 = __float2half2_rn(0.f);
    __half2 a0 = zero2, a1 = zero2, a2 = zero2, a3 = zero2;
    __half2 a4 = zero2, a5 = zero2, a6 = zero2, a7 = zero2;

#define ACC16(vv) {                                                   \
        a0 = __hadd2(a0, e4m3x2_to_h2((unsigned short)((vv).x)));     \
        a1 = __hadd2(a1, e4m3x2_to_h2((unsigned short)((vv).x >> 16)));\
        a2 = __hadd2(a2, e4m3x2_to_h2((unsigned short)((vv).y)));     \
        a3 = __hadd2(a3, e4m3x2_to_h2((unsigned short)((vv).y >> 16)));\
        a4 = __hadd2(a4, e4m3x2_to_h2((unsigned short)((vv).z)));     \
        a5 = __hadd2(a5, e4m3x2_to_h2((unsigned short)((vv).z >> 16)));\
        a6 = __hadd2(a6, e4m3x2_to_h2((unsigned short)((vv).w)));     \
        a7 = __hadd2(a7, e4m3x2_to_h2((unsigned short)((vv).w >> 16)));}

    int i = s;
    for (; i + 8 <= e; i += 8) {
        int s0 = srcs[i + ep];
        int s1 = srcs[i + 4 + ep];
        uint4 v0 = ybase[s0 * 8 + off];
        uint4 v1 = ybase[s1 * 8 + off];
        ACC16(v0); ACC16(v1);
    }
    for (; i + 4 <= e; i += 4) {
        int s0 = srcs[i + ep];
        uint4 v0 = ybase[s0 * 8 + off];
        ACC16(v0);
    }
    {
        int r = e - i;
        int sv = (ep < r) ? srcs[i + ep] : ((ep == r) ? n : -1);
        if (sv >= 0) {
            uint4 v0 = ybase[sv * 8 + off];
            ACC16(v0);
        }
    }
#undef ACC16

#define MRG(aa, d) {                                                     \
        unsigned uu = __shfl_down_sync(0xffffffffu, *(unsigned*)&(aa), d);\
        (aa) = __hadd2((aa), *(__half2*)&uu);                             }
    MRG(a0,16) MRG(a1,16) MRG(a2,16) MRG(a3,16)
    MRG(a4,16) MRG(a5,16) MRG(a6,16) MRG(a7,16)
    MRG(a0,8)  MRG(a1,8)  MRG(a2,8)  MRG(a3,8)
    MRG(a4,8)  MRG(a5,8)  MRG(a6,8)  MRG(a7,8)
#undef MRG

    if (ep == 0) {
        float di = rsqrtf((float)(degn + 1)) * (1.f / 64.f);
        float2 f0 = __half22float2(a0);
        float2 f1 = __half22float2(a1);
        float2 f2 = __half22float2(a2);
        float2 f3 = __half22float2(a3);
        float2 f4 = __half22float2(a4);
        float2 f5 = __half22float2(a5);
        float2 f6 = __half22float2(a6);
        float2 f7 = __half22float2(a7);
        __half2 h0 = __floats2half2_rn(di * f0.x, di * f0.y);
        __half2 h1 = __floats2half2_rn(di * f1.x, di * f1.y);
        __half2 h2 = __floats2half2_rn(di * f2.x, di * f2.y);
        __half2 h3 = __floats2half2_rn(di * f3.x, di * f3.y);
        __half2 h4 = __floats2half2_rn(di * f4.x, di * f4.y);
        __half2 h5 = __floats2half2_rn(di * f5.x, di * f5.y);
        __half2 h6 = __floats2half2_rn(di * f6.x, di * f6.y);
        __half2 h7 = __floats2half2_rn(di * f7.x, di * f7.y);
        uint4 o0, o1;
        o0.x = *(unsigned*)&h0; o0.y = *(unsigned*)&h1;
        o0.z = *(unsigned*)&h2; o0.w = *(unsigned*)&h3;
        o1.x = *(unsigned*)&h4; o1.y = *(unsigned*)&h5;
        o1.z = *(unsigned*)&h6; o1.w = *(unsigned*)&h7;
        uint4* zp = (uint4*)(d_z[g] + n * DD + off * 16);
        zp[0] = o0;
        zp[1] = o1;
    }
}

// ---------------- tensor-core GEMM: relu(z@W + b) column-summed ---------------
#define SMB_ZS 0
#define SMB_WT (DD * ZPH * 2)                 // 34816
#define SMB_BS (SMB_WT + DD * ZPH * 2)        // 69632
#define SMB_RED (SMB_BS + DD * 4)             // 70144
#define SMB_TOT (SMB_RED + DD * 4)            // 70656

__global__ void __launch_bounds__(256, 2)
gemm_kernel(const float* __restrict__ b1, const float* __restrict__ b2,
            const float* __restrict__ b3) {
    extern __shared__ __align__(16) char smraw[];
    __half* zs = (__half*)(smraw + SMB_ZS);
    __half* Wt = (__half*)(smraw + SMB_WT);
    float*  bs = (float*)(smraw + SMB_BS);
    float*  red = (float*)(smraw + SMB_RED);

    int g = blockIdx.y;
    const float* b = (g == 0) ? b1 : ((g == 1) ? b2 : b3);
    int t = threadIdx.x;
    int row0 = blockIdx.x * 128;

    const uint4* wsrc = (const uint4*)d_wt[g];
    for (int i = t; i < 2048; i += 256) {
        int r = i >> 4, c = i & 15;
        *(uint4*)&Wt[r * ZPH + c * 8] = wsrc[r * 16 + c];
    }
    const uint4* zsrc = (const uint4*)d_z[g];
    uint4 zz; zz.x = zz.y = zz.z = zz.w = 0u;
    for (int i = t; i < 2048; i += 256) {
        int r = i >> 4, c = i & 15;
        int row = row0 + r;
        uint4 v = (row < NN) ? zsrc[row * 16 + c] : zz;
        *(uint4*)&zs[r * ZPH + c * 8] = v;
    }
    if (t < DD) { bs[t] = b[t]; red[t] = 0.f; }
    __syncthreads();

    int lane = t & 31, w = t >> 5;
    int qr = lane >> 2;
    int q2 = (lane & 3) * 2;

    const __half* ar0 = &zs[(w * 16 + qr) * ZPH + q2];
    const __half* ar8 = ar0 + 8 * ZPH;

    float acc[16][4];
    #pragma unroll
    for (int j = 0; j < 16; j++)
        #pragma unroll
        for (int c = 0; c < 4; c++) acc[j][c] = 0.f;

    #pragma unroll
    for (int kc = 0; kc < 8; kc++) {
        int k = kc * 16;
        unsigned a0 = *(const unsigned*)(ar0 + k);
        unsigned a1 = *(const unsigned*)(ar8 + k);
        unsigned a2 = *(const unsigned*)(ar0 + k + 8);
        unsigned a3 = *(const unsigned*)(ar8 + k + 8);
        #pragma unroll
        for (int j = 0; j < 16; j++) {
            const __half* bp = &Wt[(j * 8 + qr) * ZPH + q2 + k];
            unsigned bf0 = *(const unsigned*)bp;
            unsigned bf1 = *(const unsigned*)(bp + 8);
            asm volatile(
                "mma.sync.aligned.m16n8k16.row.col.f32.f16.f16.f32 "
                "{%0,%1,%2,%3}, {%4,%5,%6,%7}, {%8,%9}, {%0,%1,%2,%3};"
                : "+f"(acc[j][0]), "+f"(acc[j][1]), "+f"(acc[j][2]), "+f"(acc[j][3])
                : "r"(a0), "r"(a1), "r"(a2), "r"(a3), "r"(bf0), "r"(bf1));
        }
    }

    int r0 = row0 + w * 16 + qr;
    int r8 = r0 + 8;
    bool v0 = r0 < NN, v8 = r8 < NN;
    #pragma unroll
    for (int j = 0; j < 16; j++) {
        int c0 = j * 8 + q2;
        float bb0 = bs[c0], bb1 = bs[c0 + 1];
        float s0 = (v0 ? fmaxf(acc[j][0] + bb0, 0.f) : 0.f)
                 + (v8 ? fmaxf(acc[j][2] + bb0, 0.f) : 0.f);
        float s1 = (v0 ? fmaxf(acc[j][1] + bb1, 0.f) : 0.f)
                 + (v8 ? fmaxf(acc[j][3] + bb1, 0.f) : 0.f);
        s0 += __shfl_down_sync(0xffffffffu, s0, 16);
        s1 += __shfl_down_sync(0xffffffffu, s1, 16);
        s0 += __shfl_down_sync(0xffffffffu, s0, 8);
        s1 += __shfl_down_sync(0xffffffffu, s1, 8);
        s0 += __shfl_down_sync(0xffffffffu, s0, 4);
        s1 += __shfl_down_sync(0xffffffffu, s1, 4);
        if (lane < 4) {
            atomicAdd(&red[c0], s0);
            atomicAdd(&red[c0 + 1], s1);
        }
    }
    __syncthreads();
    if (t < DD) atomicAdd(&d_gsum[g][t], red[t]);
}

// ---------------- head (also resets d_gsum for next call) ---------------------
__global__ void finalize_kernel(const float* __restrict__ a1w, const float* __restrict__ a1b,
                                const float* __restrict__ a2w, const float* __restrict__ a2b,
                                const float* __restrict__ a3w, const float* __restrict__ a3b,
                                const float* __restrict__ f1w, const float* __restrict__ f1b,
                                const float* __restrict__ f2w, const float* __restrict__ f2b,
                                float* __restrict__ out) {
    __shared__ float xin[3 * DD];
    __shared__ float h1[DD];
    __shared__ float h2[DD];
    __shared__ float aw[4];
    __shared__ float xa[DD];
    int t = threadIdx.x;
    xin[t]          = d_gsum[0][t];
    xin[DD + t]     = d_gsum[1][t];
    xin[2 * DD + t] = d_gsum[2][t];
    d_gsum[0][t] = 0.f;           // reset for next invocation (graph replay)
    d_gsum[1][t] = 0.f;
    d_gsum[2][t] = 0.f;
    __syncthreads();
    {
        float s = a1b[t];
        for (int j = 0; j < 3 * DD; j++) s += xin[j] * a1w[t * (3 * DD) + j];
        h1[t] = fmaxf(s, 0.f);
    }
    __syncthreads();
    {
        float s = a2b[t];
        for (int j = 0; j < DD; j++) s += h1[j] * a2w[t * DD + j];
        h2[t] = s;
    }
    __syncthreads();
    if (t < 3) {
        float s = a3b[t];
        for (int j = 0; j < DD; j++) s += fmaxf(h2[j], 0.f) * a3w[t * DD + j];
        aw[t] = s;
    }
    __syncthreads();
    if (t == 0) {
        float m = fmaxf(aw[0], fmaxf(aw[1], aw[2]));
        float e0 = expf(aw[0] - m), e1 = expf(aw[1] - m), e2 = expf(aw[2] - m);
        float S = e0 + e1 + e2;
        aw[0] = e0 / S; aw[1] = e1 / S; aw[2] = e2 / S;
    }
    __syncthreads();
    xa[t] = aw[0] * xin[t] + aw[1] * xin[DD + t] + aw[2] * xin[2 * DD + t];
    __syncthreads();
    float sg = f1b[t], sb = f2b[t];
    for (int j = 0; j < DD; j++) {
        float v = xa[j];
        sg += v * f1w[t * DD + j];
        sb += v * f2w[t * DD + j];
    }
    out[t]      = tanhf(sg);
    out[DD + t] = tanhf(sb);
}

// ---------------- launch ------------------------------------------------------
extern "C" void kernel_launch(void* const* d_in, const int* in_sizes, int n_in,
                              void* d_out, int out_size) {
    const float* x1 = (const float*)d_in[0];
    const float* x2 = (const float*)d_in[1];
    const float* x3 = (const float*)d_in[2];
    const int* e1 = (const int*)d_in[3];
    const int* e2 = (const int*)d_in[4];
    const int* e3 = (const int*)d_in[5];
    const float* W1 = (const float*)d_in[6];  const float* b1 = (const float*)d_in[7];
    const float* W2 = (const float*)d_in[8];  const float* b2 = (const float*)d_in[9];
    const float* W3 = (const float*)d_in[10]; const float* b3 = (const float*)d_in[11];
    const float* a1w = (const float*)d_in[12]; const float* a1b = (const float*)d_in[13];
    const float* a2w = (const float*)d_in[14]; const float* a2b = (const float*)d_in[15];
    const float* a3w = (const float*)d_in[16]; const float* a3b = (const float*)d_in[17];
    const float* f1w = (const float*)d_in[18]; const float* f1b = (const float*)d_in[19];
    const float* f2w = (const float*)d_in[20]; const float* f2b = (const float*)d_in[21];
    float* out = (float*)d_out;

    static bool attr_set = false;
    if (!attr_set) {
        cudaFuncSetAttribute(gemm_kernel, cudaFuncAttributeMaxDynamicSharedMemorySize,
                             SMB_TOT);
        attr_set = true;
    }

    hist_kernel<<<dim3(256, NG), 256>>>(e1, e2, e3);
    scan_kernel<<<NG, 1024>>>();
    fill_convert_kernel<<<dim3(772, NG), 256>>>(e1, e2, e3, x1, x2, x3, W1, W2, W3);
    gather_kernel<<<dim3((NN + 7) / 8, NG), 256>>>();
    gemm_kernel<<<dim3(NT128, NG), 256, SMB_TOT>>>(b1, b2, b3);
    finalize_kernel<<<1, DD>>>(a1w, a1b, a2w, a2b, a3w, a3b, f1w, f1b, f2w, f2b, out);
}

// round 13
// speedup vs baseline: 2.1855x; 2.1855x over previous
#include <cuda_runtime.h>
#include <cuda_fp16.h>
#include <math.h>

#define NN 50000
#define NE 800000
#define DD 128
#define NG 3
#define NSCAN 13
#define NT128 ((NN + 127) / 128)   // 391
#define ZPH 136                    // padded row pitch in halves

// ---------------- scratch ----------------------------------------------------
__device__ int           d_deg[NG][NN];       // zeroed statically; reset by scan_pass3 after read
__device__ int           d_start[NG][NN + 1];
__device__ int           d_cursor[NG][NN];
__device__ int           d_srcs[NG][NE];
__device__ float         d_dinv[NG][NN];
__device__ unsigned char d_y8[NG][NN * DD];   // fp8 e4m3 of 64*dinv[n]*x[n]
__device__ __half        d_z[NG][NN * DD];    // aggregated features (fp16)
__device__ __half        d_wt[NG][DD * DD];   // W transposed fp16
__device__ float         d_gsum[NG][DD];      // zeroed statically; reset by finalize
__device__ int           d_bsum[NG][16];

// ---------------- fp8 helpers -------------------------------------------------
__device__ __forceinline__ unsigned short f32x2_to_e4m3x2(float lo, float hi) {
    unsigned short r;
    asm("cvt.rn.satfinite.e4m3x2.f32 %0, %1, %2;" : "=h"(r) : "f"(hi), "f"(lo));
    return r;
}
__device__ __forceinline__ __half2 e4m3x2_to_h2(unsigned short u) {
    unsigned r;
    asm("cvt.rn.f16x2.e4m3x2 %0, %1;" : "=r"(r) : "h"(u));
    return *(__half2*)&r;
}

// ---------------- hist --------------------------------------------------------
__global__ void hist_kernel(const int* __restrict__ e1,
                            const int* __restrict__ e2,
                            const int* __restrict__ e3) {
    int g = blockIdx.y;
    const int* ei = (g == 0) ? e1 : ((g == 1) ? e2 : e3);
    const int4* dst4 = (const int4*)(ei + NE);
    int stride = gridDim.x * blockDim.x;
    for (int i = blockIdx.x * blockDim.x + threadIdx.x; i < NE / 4; i += stride) {
        int4 d = dst4[i];
        atomicAdd(&d_deg[g][d.x], 1);
        atomicAdd(&d_deg[g][d.y], 1);
        atomicAdd(&d_deg[g][d.z], 1);
        atomicAdd(&d_deg[g][d.w], 1);
    }
}

__global__ void scan_pass1() {   // grid (NSCAN, NG) x 256: block sums
    int g = blockIdx.y;
    int t = threadIdx.x;
    int base = blockIdx.x * 4096 + t * 16;
    int s = 0;
    #pragma unroll
    for (int i = 0; i < 16; i++) {
        int idx = base + i;
        if (idx < NN) s += d_deg[g][idx];
    }
    #pragma unroll
    for (int o = 16; o; o >>= 1) s += __shfl_down_sync(0xffffffffu, s, o);
    __shared__ int ws[8];
    if ((t & 31) == 0) ws[t >> 5] = s;
    __syncthreads();
    if (t == 0) {
        int v = 0;
        #pragma unroll
        for (int w = 0; w < 8; w++) v += ws[w];
        d_bsum[g][blockIdx.x] = v;
    }
}

__global__ void scan_pass3() {   // grid (NSCAN, NG) x 256; resets deg after reading
    int g = blockIdx.y;
    int t = threadIdx.x;
    __shared__ int bofs;
    if (t == 0) {
        int run = 0;
        for (int i = 0; i < (int)blockIdx.x; i++) run += d_bsum[g][i];
        bofs = run;
    }
    int base = blockIdx.x * 4096 + t * 16;
    int v[16];
    int s = 0;
    #pragma unroll
    for (int i = 0; i < 16; i++) {
        int idx = base + i;
        v[i] = (idx < NN) ? d_deg[g][idx] : 0;
        s += v[i];
    }
    int incl = s;
    #pragma unroll
    for (int o = 1; o < 32; o <<= 1) {
        int y = __shfl_up_sync(0xffffffffu, incl, o);
        if ((t & 31) >= o) incl += y;
    }
    __shared__ int ws[8];
    if ((t & 31) == 31) ws[t >> 5] = incl;
    __syncthreads();
    if (t == 0) {
        int run = 0;
        #pragma unroll
        for (int w = 0; w < 8; w++) { int tmp = ws[w]; ws[w] = run; run += tmp; }
    }
    __syncthreads();
    int run = bofs + ws[t >> 5] + (incl - s);
    #pragma unroll
    for (int i = 0; i < 16; i++) {
        int idx = base + i;
        if (idx < NN) {
            d_start[g][idx]  = run;
            d_cursor[g][idx] = run;
            d_dinv[g][idx]   = rsqrtf((float)(v[i] + 1));
            d_deg[g][idx]    = 0;                     // reset for next invocation
            run += v[i];
        }
    }
    if (t == 0 && blockIdx.x == 0) d_start[g][NN] = NE;
}

// ---------------- merged fill + convert (x->fp8) + W transpose ----------------
// grid (772, NG): bx<256 fill, 256<=bx<768 convert, bx>=768 W transpose
__global__ void fill_convert_kernel(const int* __restrict__ e1,
                                    const int* __restrict__ e2,
                                    const int* __restrict__ e3,
                                    const float* __restrict__ x1,
                                    const float* __restrict__ x2,
                                    const float* __restrict__ x3,
                                    const float* __restrict__ W1,
                                    const float* __restrict__ W2,
                                    const float* __restrict__ W3) {
    int g = blockIdx.y;
    int t = threadIdx.x;
    int bx = blockIdx.x;

    if (bx < 256) {
        // ---- fill CSR ----
        const int* ei = (g == 0) ? e1 : ((g == 1) ? e2 : e3);
        const int4* src4 = (const int4*)ei;
        const int4* dst4 = (const int4*)(ei + NE);
        int stride = 256 * 256;
        int* srcs = d_srcs[g];
        int* cur  = d_cursor[g];
        for (int i = bx * 256 + t; i < NE / 4; i += stride) {
            int4 sv = src4[i];
            int4 dv = dst4[i];
            srcs[atomicAdd(&cur[dv.x], 1)] = sv.x;
            srcs[atomicAdd(&cur[dv.y], 1)] = sv.y;
            srcs[atomicAdd(&cur[dv.z], 1)] = sv.z;
            srcs[atomicAdd(&cur[dv.w], 1)] = sv.w;
        }
    } else if (bx < 768) {
        // ---- convert x -> fp8 y8 (reads d_dinv, as R8) ----
        const float4* x4 = (const float4*)((g == 0) ? x1 : ((g == 1) ? x2 : x3));
        const float* dinv = d_dinv[g];
        uint4* y4 = (uint4*)d_y8[g];
        int stride = 512 * 256;
        for (int i = (bx - 256) * 256 + t; i < NN * 8; i += stride) {
            int n = i >> 3;
            int c = i & 7;
            float sc = 64.f * dinv[n];
            const float4* xp = x4 + n * 32 + c * 4;
            float4 v0 = xp[0], v1 = xp[1], v2 = xp[2], v3 = xp[3];
            unsigned short s0 = f32x2_to_e4m3x2(sc * v0.x, sc * v0.y);
            unsigned short s1 = f32x2_to_e4m3x2(sc * v0.z, sc * v0.w);
            unsigned short s2 = f32x2_to_e4m3x2(sc * v1.x, sc * v1.y);
            unsigned short s3 = f32x2_to_e4m3x2(sc * v1.z, sc * v1.w);
            unsigned short s4 = f32x2_to_e4m3x2(sc * v2.x, sc * v2.y);
            unsigned short s5 = f32x2_to_e4m3x2(sc * v2.z, sc * v2.w);
            unsigned short s6 = f32x2_to_e4m3x2(sc * v3.x, sc * v3.y);
            unsigned short s7 = f32x2_to_e4m3x2(sc * v3.z, sc * v3.w);
            uint4 o;
            o.x = (unsigned)s0 | ((unsigned)s1 << 16);
            o.y = (unsigned)s2 | ((unsigned)s3 << 16);
            o.z = (unsigned)s4 | ((unsigned)s5 << 16);
            o.w = (unsigned)s6 | ((unsigned)s7 << 16);
            y4[i] = o;
        }
    } else {
        // ---- W transpose -> fp16 ----
        const float* W = (g == 0) ? W1 : ((g == 1) ? W2 : W3);
        __half* wt = d_wt[g];
        int gid = (bx - 768) * 256 + t;   // 0..1023
        int j = gid >> 3;
        int k0 = (gid & 7) * 16;
        #pragma unroll
        for (int kk = 0; kk < 16; kk++)
            wt[j * DD + k0 + kk] = __float2half(W[(k0 + kk) * DD + j]);
    }
}

// ---------------- gather (fp8 reads, fp16 accum) — EXACT R8 form --------------
__global__ void gather_kernel() {
    int g = blockIdx.y;
    const uint4* ybase = (const uint4*)d_y8[g];   // row = 8 uint4
    int warp = (blockIdx.x * blockDim.x + threadIdx.x) >> 5;
    int lane = threadIdx.x & 31;
    if (warp >= NN) return;
    int n = warp;
    int ep  = lane >> 3;        // edge slot 0..3
    int off = lane & 7;         // 16B chunk within row
    int s = d_start[g][n];
    int e = d_start[g][n + 1];
    const int* srcs = d_srcs[g];

    __half2 zero2 = __float2half2_rn(0.f);
    __half2 a0 = zero2, a1 = zero2, a2 = zero2, a3 = zero2;
    __half2 a4 = zero2, a5 = zero2, a6 = zero2, a7 = zero2;

#define ACC16(vv) {                                                   \
        a0 = __hadd2(a0, e4m3x2_to_h2((unsigned short)((vv).x)));     \
        a1 = __hadd2(a1, e4m3x2_to_h2((unsigned short)((vv).x >> 16)));\
        a2 = __hadd2(a2, e4m3x2_to_h2((unsigned short)((vv).y)));     \
        a3 = __hadd2(a3, e4m3x2_to_h2((unsigned short)((vv).y >> 16)));\
        a4 = __hadd2(a4, e4m3x2_to_h2((unsigned short)((vv).z)));     \
        a5 = __hadd2(a5, e4m3x2_to_h2((unsigned short)((vv).z >> 16)));\
        a6 = __hadd2(a6, e4m3x2_to_h2((unsigned short)((vv).w)));     \
        a7 = __hadd2(a7, e4m3x2_to_h2((unsigned short)((vv).w >> 16)));}

    int i = s;
    for (; i + 8 <= e; i += 8) {
        int s0 = srcs[i + ep];
        int s1 = srcs[i + 4 + ep];
        uint4 v0 = ybase[s0 * 8 + off];
        uint4 v1 = ybase[s1 * 8 + off];
        ACC16(v0); ACC16(v1);
    }
    for (; i + 4 <= e; i += 4) {
        int s0 = srcs[i + ep];
        uint4 v0 = ybase[s0 * 8 + off];
        ACC16(v0);
    }
    {
        int r = e - i;
        int sv = (ep < r) ? srcs[i + ep] : ((ep == r) ? n : -1);
        if (sv >= 0) {
            uint4 v0 = ybase[sv * 8 + off];
            ACC16(v0);
        }
    }
#undef ACC16

#define MRG(aa, d) {                                                     \
        unsigned uu = __shfl_down_sync(0xffffffffu, *(unsigned*)&(aa), d);\
        (aa) = __hadd2((aa), *(__half2*)&uu);                             }
    MRG(a0,16) MRG(a1,16) MRG(a2,16) MRG(a3,16)
    MRG(a4,16) MRG(a5,16) MRG(a6,16) MRG(a7,16)
    MRG(a0,8)  MRG(a1,8)  MRG(a2,8)  MRG(a3,8)
    MRG(a4,8)  MRG(a5,8)  MRG(a6,8)  MRG(a7,8)
#undef MRG

    if (ep == 0) {
        float di = d_dinv[g][n] * (1.f / 64.f);
        float2 f0 = __half22float2(a0);
        float2 f1 = __half22float2(a1);
        float2 f2 = __half22float2(a2);
        float2 f3 = __half22float2(a3);
        float2 f4 = __half22float2(a4);
        float2 f5 = __half22float2(a5);
        float2 f6 = __half22float2(a6);
        float2 f7 = __half22float2(a7);
        __half2 h0 = __floats2half2_rn(di * f0.x, di * f0.y);
        __half2 h1 = __floats2half2_rn(di * f1.x, di * f1.y);
        __half2 h2 = __floats2half2_rn(di * f2.x, di * f2.y);
        __half2 h3 = __floats2half2_rn(di * f3.x, di * f3.y);
        __half2 h4 = __floats2half2_rn(di * f4.x, di * f4.y);
        __half2 h5 = __floats2half2_rn(di * f5.x, di * f5.y);
        __half2 h6 = __floats2half2_rn(di * f6.x, di * f6.y);
        __half2 h7 = __floats2half2_rn(di * f7.x, di * f7.y);
        uint4 o0, o1;
        o0.x = *(unsigned*)&h0; o0.y = *(unsigned*)&h1;
        o0.z = *(unsigned*)&h2; o0.w = *(unsigned*)&h3;
        o1.x = *(unsigned*)&h4; o1.y = *(unsigned*)&h5;
        o1.z = *(unsigned*)&h6; o1.w = *(unsigned*)&h7;
        uint4* zp = (uint4*)(d_z[g] + n * DD + off * 16);
        zp[0] = o0;
        zp[1] = o1;
    }
}

// ---------------- tensor-core GEMM: relu(z@W + b) column-summed ---------------
#define SMB_ZS 0
#define SMB_WT (DD * ZPH * 2)                 // 34816
#define SMB_BS (SMB_WT + DD * ZPH * 2)        // 69632
#define SMB_RED (SMB_BS + DD * 4)             // 70144
#define SMB_TOT (SMB_RED + DD * 4)            // 70656

__global__ void __launch_bounds__(256, 2)
gemm_kernel(const float* __restrict__ b1, const float* __restrict__ b2,
            const float* __restrict__ b3) {
    extern __shared__ __align__(16) char smraw[];
    __half* zs = (__half*)(smraw + SMB_ZS);
    __half* Wt = (__half*)(smraw + SMB_WT);
    float*  bs = (float*)(smraw + SMB_BS);
    float*  red = (float*)(smraw + SMB_RED);

    int g = blockIdx.y;
    const float* b = (g == 0) ? b1 : ((g == 1) ? b2 : b3);
    int t = threadIdx.x;
    int row0 = blockIdx.x * 128;

    const uint4* wsrc = (const uint4*)d_wt[g];
    for (int i = t; i < 2048; i += 256) {
        int r = i >> 4, c = i & 15;
        *(uint4*)&Wt[r * ZPH + c * 8] = wsrc[r * 16 + c];
    }
    const uint4* zsrc = (const uint4*)d_z[g];
    uint4 zz; zz.x = zz.y = zz.z = zz.w = 0u;
    for (int i = t; i < 2048; i += 256) {
        int r = i >> 4, c = i & 15;
        int row = row0 + r;
        uint4 v = (row < NN) ? zsrc[row * 16 + c] : zz;
        *(uint4*)&zs[r * ZPH + c * 8] = v;
    }
    if (t < DD) { bs[t] = b[t]; red[t] = 0.f; }
    __syncthreads();

    int lane = t & 31, w = t >> 5;
    int qr = lane >> 2;
    int q2 = (lane & 3) * 2;

    const __half* ar0 = &zs[(w * 16 + qr) * ZPH + q2];
    const __half* ar8 = ar0 + 8 * ZPH;

    float acc[16][4];
    #pragma unroll
    for (int j = 0; j < 16; j++)
        #pragma unroll
        for (int c = 0; c < 4; c++) acc[j][c] = 0.f;

    #pragma unroll
    for (int kc = 0; kc < 8; kc++) {
        int k = kc * 16;
        unsigned a0 = *(const unsigned*)(ar0 + k);
        unsigned a1 = *(const unsigned*)(ar8 + k);
        unsigned a2 = *(const unsigned*)(ar0 + k + 8);
        unsigned a3 = *(const unsigned*)(ar8 + k + 8);
        #pragma unroll
        for (int j = 0; j < 16; j++) {
            const __half* bp = &Wt[(j * 8 + qr) * ZPH + q2 + k];
            unsigned bf0 = *(const unsigned*)bp;
            unsigned bf1 = *(const unsigned*)(bp + 8);
            asm volatile(
                "mma.sync.aligned.m16n8k16.row.col.f32.f16.f16.f32 "
                "{%0,%1,%2,%3}, {%4,%5,%6,%7}, {%8,%9}, {%0,%1,%2,%3};"
                : "+f"(acc[j][0]), "+f"(acc[j][1]), "+f"(acc[j][2]), "+f"(acc[j][3])
                : "r"(a0), "r"(a1), "r"(a2), "r"(a3), "r"(bf0), "r"(bf1));
        }
    }

    int r0 = row0 + w * 16 + qr;
    int r8 = r0 + 8;
    bool v0 = r0 < NN, v8 = r8 < NN;
    #pragma unroll
    for (int j = 0; j < 16; j++) {
        int c0 = j * 8 + q2;
        float bb0 = bs[c0], bb1 = bs[c0 + 1];
        float s0 = (v0 ? fmaxf(acc[j][0] + bb0, 0.f) : 0.f)
                 + (v8 ? fmaxf(acc[j][2] + bb0, 0.f) : 0.f);
        float s1 = (v0 ? fmaxf(acc[j][1] + bb1, 0.f) : 0.f)
                 + (v8 ? fmaxf(acc[j][3] + bb1, 0.f) : 0.f);
        s0 += __shfl_down_sync(0xffffffffu, s0, 16);
        s1 += __shfl_down_sync(0xffffffffu, s1, 16);
        s0 += __shfl_down_sync(0xffffffffu, s0, 8);
        s1 += __shfl_down_sync(0xffffffffu, s1, 8);
        s0 += __shfl_down_sync(0xffffffffu, s0, 4);
        s1 += __shfl_down_sync(0xffffffffu, s1, 4);
        if (lane < 4) {
            atomicAdd(&red[c0], s0);
            atomicAdd(&red[c0 + 1], s1);
        }
    }
    __syncthreads();
    if (t < DD) atomicAdd(&d_gsum[g][t], red[t]);
}

// ---------------- head (also resets d_gsum for next call) ---------------------
__global__ void finalize_kernel(const float* __restrict__ a1w, const float* __restrict__ a1b,
                                const float* __restrict__ a2w, const float* __restrict__ a2b,
                                const float* __restrict__ a3w, const float* __restrict__ a3b,
                                const float* __restrict__ f1w, const float* __restrict__ f1b,
                                const float* __restrict__ f2w, const float* __restrict__ f2b,
                                float* __restrict__ out) {
    __shared__ float xin[3 * DD];
    __shared__ float h1[DD];
    __shared__ float h2[DD];
    __shared__ float aw[4];
    __shared__ float xa[DD];
    int t = threadIdx.x;
    xin[t]          = d_gsum[0][t];
    xin[DD + t]     = d_gsum[1][t];
    xin[2 * DD + t] = d_gsum[2][t];
    d_gsum[0][t] = 0.f;           // reset for next invocation (graph replay)
    d_gsum[1][t] = 0.f;
    d_gsum[2][t] = 0.f;
    __syncthreads();
    {
        float s = a1b[t];
        for (int j = 0; j < 3 * DD; j++) s += xin[j] * a1w[t * (3 * DD) + j];
        h1[t] = fmaxf(s, 0.f);
    }
    __syncthreads();
    {
        float s = a2b[t];
        for (int j = 0; j < DD; j++) s += h1[j] * a2w[t * DD + j];
        h2[t] = s;
    }
    __syncthreads();
    if (t < 3) {
        float s = a3b[t];
        for (int j = 0; j < DD; j++) s += fmaxf(h2[j], 0.f) * a3w[t * DD + j];
        aw[t] = s;
    }
    __syncthreads();
    if (t == 0) {
        float m = fmaxf(aw[0], fmaxf(aw[1], aw[2]));
        float e0 = expf(aw[0] - m), e1 = expf(aw[1] - m), e2 = expf(aw[2] - m);
        float S = e0 + e1 + e2;
        aw[0] = e0 / S; aw[1] = e1 / S; aw[2] = e2 / S;
    }
    __syncthreads();
    xa[t] = aw[0] * xin[t] + aw[1] * xin[DD + t] + aw[2] * xin[2 * DD + t];
    __syncthreads();
    float sg = f1b[t], sb = f2b[t];
    for (int j = 0; j < DD; j++) {
        float v = xa[j];
        sg += v * f1w[t * DD + j];
        sb += v * f2w[t * DD + j];
    }
    out[t]      = tanhf(sg);
    out[DD + t] = tanhf(sb);
}

// ---------------- launch ------------------------------------------------------
extern "C" void kernel_launch(void* const* d_in, const int* in_sizes, int n_in,
                              void* d_out, int out_size) {
    const float* x1 = (const float*)d_in[0];
    const float* x2 = (const float*)d_in[1];
    const float* x3 = (const float*)d_in[2];
    const int* e1 = (const int*)d_in[3];
    const int* e2 = (const int*)d_in[4];
    const int* e3 = (const int*)d_in[5];
    const float* W1 = (const float*)d_in[6];  const float* b1 = (const float*)d_in[7];
    const float* W2 = (const float*)d_in[8];  const float* b2 = (const float*)d_in[9];
    const float* W3 = (const float*)d_in[10]; const float* b3 = (const float*)d_in[11];
    const float* a1w = (const float*)d_in[12]; const float* a1b = (const float*)d_in[13];
    const float* a2w = (const float*)d_in[14]; const float* a2b = (const float*)d_in[15];
    const float* a3w = (const float*)d_in[16]; const float* a3b = (const float*)d_in[17];
    const float* f1w = (const float*)d_in[18]; const float* f1b = (const float*)d_in[19];
    const float* f2w = (const float*)d_in[20]; const float* f2b = (const float*)d_in[21];
    float* out = (float*)d_out;

    static bool attr_set = false;
    if (!attr_set) {
        cudaFuncSetAttribute(gemm_kernel, cudaFuncAttributeMaxDynamicSharedMemorySize,
                             SMB_TOT);
        attr_set = true;
    }

    hist_kernel<<<dim3(256, NG), 256>>>(e1, e2, e3);
    scan_pass1<<<dim3(NSCAN, NG), 256>>>();
    scan_pass3<<<dim3(NSCAN, NG), 256>>>();
    fill_convert_kernel<<<dim3(772, NG), 256>>>(e1, e2, e3, x1, x2, x3, W1, W2, W3);
    gather_kernel<<<dim3((NN + 7) / 8, NG), 256>>>();
    gemm_kernel<<<dim3(NT128, NG), 256, SMB_TOT>>>(b1, b2, b3);
    finalize_kernel<<<1, DD>>>(a1w, a1b, a2w, a2b, a3w, a3b, f1w, f1b, f2w, f2b, out);
}

// round 15
// speedup vs baseline: 2.2852x; 1.0456x over previous
#include <cuda_runtime.h>
#include <cuda_fp16.h>
#include <math.h>

#define NN 50000
#define NE 800000
#define DD 128
#define NG 3
#define NSCAN 13
#define NT128 ((NN + 127) / 128)   // 391
#define ZPH 136                    // padded row pitch in halves

// ---------------- scratch ----------------------------------------------------
__device__ int           d_deg[NG][NN];       // zeroed statically; reset by fill_convert sec4
__device__ int           d_start[NG][NN + 1];
__device__ int           d_cursor[NG][NN];
__device__ int           d_srcs[NG][NE];
__device__ float         d_dinv[NG][NN];
__device__ unsigned char d_y8[NG][NN * DD];   // fp8 e4m3 of 64*dinv[n]*x[n]
__device__ unsigned char d_z8[NG][NN * DD];   // fp8 e4m3 of 64*z (aggregated)
__device__ __half        d_wt[NG][DD * DD];   // (W/64) transposed fp16
__device__ float         d_gsum[NG][DD];      // zeroed statically; reset by finalize

// ---------------- fp8 helpers -------------------------------------------------
__device__ __forceinline__ unsigned short f32x2_to_e4m3x2(float lo, float hi) {
    unsigned short r;
    asm("cvt.rn.satfinite.e4m3x2.f32 %0, %1, %2;" : "=h"(r) : "f"(hi), "f"(lo));
    return r;
}
__device__ __forceinline__ __half2 e4m3x2_to_h2(unsigned short u) {
    unsigned r;
    asm("cvt.rn.f16x2.e4m3x2 %0, %1;" : "=r"(r) : "h"(u));
    return *(__half2*)&r;
}

// ---------------- hist --------------------------------------------------------
__global__ void hist_kernel(const int* __restrict__ e1,
                            const int* __restrict__ e2,
                            const int* __restrict__ e3) {
    int g = blockIdx.y;
    const int* ei = (g == 0) ? e1 : ((g == 1) ? e2 : e3);
    const int4* dst4 = (const int4*)(ei + NE);
    int stride = gridDim.x * blockDim.x;
    for (int i = blockIdx.x * blockDim.x + threadIdx.x; i < NE / 4; i += stride) {
        int4 d = dst4[i];
        atomicAdd(&d_deg[g][d.x], 1);
        atomicAdd(&d_deg[g][d.y], 1);
        atomicAdd(&d_deg[g][d.z], 1);
        atomicAdd(&d_deg[g][d.w], 1);
    }
}

// ---------------- single-pass scan: grid (NSCAN, NG) x 256 --------------------
// Each block recomputes its prefix base from preceding deg chunks; then does the
// local scan and emits start/cursor/dinv. deg is NOT reset here (readers race).
__global__ void scan_kernel() {
    int g = blockIdx.y;
    int bx = blockIdx.x;
    int t = threadIdx.x;
    int lane = t & 31, wid = t >> 5;
    const int4* deg4 = (const int4*)d_deg[g];

    // prefix base = sum of deg[0 .. bx*4096)
    int pre = 0;
    int nPrev4 = bx * 1024;
    for (int i = t; i < nPrev4; i += 256) {
        int4 v = deg4[i];
        pre += v.x + v.y + v.z + v.w;
    }
    #pragma unroll
    for (int o = 16; o; o >>= 1) pre += __shfl_down_sync(0xffffffffu, pre, o);
    __shared__ int red8[8];
    __shared__ int bofs;
    if (lane == 0) red8[wid] = pre;
    __syncthreads();
    if (t == 0) {
        int s = 0;
        #pragma unroll
        for (int w = 0; w < 8; w++) s += red8[w];
        bofs = s;
    }

    // local chunk scan
    int base = bx * 4096 + t * 16;
    int v[16];
    int s = 0;
    #pragma unroll
    for (int i = 0; i < 16; i++) {
        int idx = base + i;
        v[i] = (idx < NN) ? d_deg[g][idx] : 0;
        s += v[i];
    }
    int incl = s;
    #pragma unroll
    for (int o = 1; o < 32; o <<= 1) {
        int y = __shfl_up_sync(0xffffffffu, incl, o);
        if (lane >= o) incl += y;
    }
    __shared__ int ws[8];
    if (lane == 31) ws[wid] = incl;
    __syncthreads();
    if (t == 0) {
        int run = 0;
        #pragma unroll
        for (int w = 0; w < 8; w++) { int tmp = ws[w]; ws[w] = run; run += tmp; }
    }
    __syncthreads();
    int run = bofs + ws[wid] + (incl - s);
    #pragma unroll
    for (int i = 0; i < 16; i++) {
        int idx = base + i;
        if (idx < NN) {
            d_start[g][idx]  = run;
            d_cursor[g][idx] = run;
            d_dinv[g][idx]   = rsqrtf((float)(v[i] + 1));
            run += v[i];
        }
    }
    if (t == 0 && bx == 0) d_start[g][NN] = NE;
}

// ---------------- merged fill + convert + W transpose + deg reset -------------
// grid (1076, NG): [0,512) fill, [512,1024) convert, [1024,1028) W, [1028,1076) deg reset
__global__ void fill_convert_kernel(const int* __restrict__ e1,
                                    const int* __restrict__ e2,
                                    const int* __restrict__ e3,
                                    const float* __restrict__ x1,
                                    const float* __restrict__ x2,
                                    const float* __restrict__ x3,
                                    const float* __restrict__ W1,
                                    const float* __restrict__ W2,
                                    const float* __restrict__ W3) {
    int g = blockIdx.y;
    int t = threadIdx.x;
    int bx = blockIdx.x;

    if (bx < 512) {
        // ---- fill CSR ----
        const int* ei = (g == 0) ? e1 : ((g == 1) ? e2 : e3);
        const int4* src4 = (const int4*)ei;
        const int4* dst4 = (const int4*)(ei + NE);
        int stride = 512 * 256;
        int* srcs = d_srcs[g];
        int* cur  = d_cursor[g];
        for (int i = bx * 256 + t; i < NE / 4; i += stride) {
            int4 sv = src4[i];
            int4 dv = dst4[i];
            srcs[atomicAdd(&cur[dv.x], 1)] = sv.x;
            srcs[atomicAdd(&cur[dv.y], 1)] = sv.y;
            srcs[atomicAdd(&cur[dv.z], 1)] = sv.z;
            srcs[atomicAdd(&cur[dv.w], 1)] = sv.w;
        }
    } else if (bx < 1024) {
        // ---- convert x -> fp8 y8 ----
        const float4* x4 = (const float4*)((g == 0) ? x1 : ((g == 1) ? x2 : x3));
        const float* dinv = d_dinv[g];
        uint4* y4 = (uint4*)d_y8[g];
        int stride = 512 * 256;
        for (int i = (bx - 512) * 256 + t; i < NN * 8; i += stride) {
            int n = i >> 3;
            int c = i & 7;
            float sc = 64.f * dinv[n];
            const float4* xp = x4 + n * 32 + c * 4;
            float4 v0 = xp[0], v1 = xp[1], v2 = xp[2], v3 = xp[3];
            unsigned short s0 = f32x2_to_e4m3x2(sc * v0.x, sc * v0.y);
            unsigned short s1 = f32x2_to_e4m3x2(sc * v0.z, sc * v0.w);
            unsigned short s2 = f32x2_to_e4m3x2(sc * v1.x, sc * v1.y);
            unsigned short s3 = f32x2_to_e4m3x2(sc * v1.z, sc * v1.w);
            unsigned short s4 = f32x2_to_e4m3x2(sc * v2.x, sc * v2.y);
            unsigned short s5 = f32x2_to_e4m3x2(sc * v2.z, sc * v2.w);
            unsigned short s6 = f32x2_to_e4m3x2(sc * v3.x, sc * v3.y);
            unsigned short s7 = f32x2_to_e4m3x2(sc * v3.z, sc * v3.w);
            uint4 o;
            o.x = (unsigned)s0 | ((unsigned)s1 << 16);
            o.y = (unsigned)s2 | ((unsigned)s3 << 16);
            o.z = (unsigned)s4 | ((unsigned)s5 << 16);
            o.w = (unsigned)s6 | ((unsigned)s7 << 16);
            y4[i] = o;
        }
    } else if (bx < 1028) {
        // ---- W transpose -> fp16, pre-scaled by 1/64 (z carries 64x) ----
        const float* W = (g == 0) ? W1 : ((g == 1) ? W2 : W3);
        __half* wt = d_wt[g];
        int gid = (bx - 1024) * 256 + t;   // 0..1023
        int j = gid >> 3;
        int k0 = (gid & 7) * 16;
        #pragma unroll
        for (int kk = 0; kk < 16; kk++)
            wt[j * DD + k0 + kk] = __float2half(W[(k0 + kk) * DD + j] * (1.f / 64.f));
    } else {
        // ---- reset deg for next invocation (scan has finished reading it) ----
        int4* deg4 = (int4*)d_deg[g];
        int4 z4 = make_int4(0, 0, 0, 0);
        int stride = 48 * 256;
        for (int i = (bx - 1028) * 256 + t; i < NN / 4; i += stride) deg4[i] = z4;
    }
}

// ---------------- gather (fp8 reads, fp16 accum, fp8 z out) -------------------
__global__ void gather_kernel() {
    int g = blockIdx.y;
    const uint4* ybase = (const uint4*)d_y8[g];   // row = 8 uint4
    int warp = (blockIdx.x * blockDim.x + threadIdx.x) >> 5;
    int lane = threadIdx.x & 31;
    if (warp >= NN) return;
    int n = warp;
    int ep  = lane >> 3;        // edge slot 0..3
    int off = lane & 7;         // 16B chunk within row
    int s = d_start[g][n];
    int e = d_start[g][n + 1];
    const int* srcs = d_srcs[g];

    __half2 zero2 = __float2half2_rn(0.f);
    __half2 a0 = zero2, a1 = zero2, a2 = zero2, a3 = zero2;
    __half2 a4 = zero2, a5 = zero2, a6 = zero2, a7 = zero2;

#define ACC16(vv) {                                                   \
        a0 = __hadd2(a0, e4m3x2_to_h2((unsigned short)((vv).x)));     \
        a1 = __hadd2(a1, e4m3x2_to_h2((unsigned short)((vv).x >> 16)));\
        a2 = __hadd2(a2, e4m3x2_to_h2((unsigned short)((vv).y)));     \
        a3 = __hadd2(a3, e4m3x2_to_h2((unsigned short)((vv).y >> 16)));\
        a4 = __hadd2(a4, e4m3x2_to_h2((unsigned short)((vv).z)));     \
        a5 = __hadd2(a5, e4m3x2_to_h2((unsigned short)((vv).z >> 16)));\
        a6 = __hadd2(a6, e4m3x2_to_h2((unsigned short)((vv).w)));     \
        a7 = __hadd2(a7, e4m3x2_to_h2((unsigned short)((vv).w >> 16)));}

    int i = s;
    for (; i + 8 <= e; i += 8) {
        int s0 = srcs[i + ep];
        int s1 = srcs[i + 4 + ep];
        uint4 v0 = ybase[s0 * 8 + off];
        uint4 v1 = ybase[s1 * 8 + off];
        ACC16(v0); ACC16(v1);
    }
    for (; i + 4 <= e; i += 4) {
        int s0 = srcs[i + ep];
        uint4 v0 = ybase[s0 * 8 + off];
        ACC16(v0);
    }
    {
        int r = e - i;
        int sv = (ep < r) ? srcs[i + ep] : ((ep == r) ? n : -1);
        if (sv >= 0) {
            uint4 v0 = ybase[sv * 8 + off];
            ACC16(v0);
        }
    }
#undef ACC16

#define MRG(aa, d) {                                                     \
        unsigned uu = __shfl_down_sync(0xffffffffu, *(unsigned*)&(aa), d);\
        (aa) = __hadd2((aa), *(__half2*)&uu);                             }
    MRG(a0,16) MRG(a1,16) MRG(a2,16) MRG(a3,16)
    MRG(a4,16) MRG(a5,16) MRG(a6,16) MRG(a7,16)
    MRG(a0,8)  MRG(a1,8)  MRG(a2,8)  MRG(a3,8)
    MRG(a4,8)  MRG(a5,8)  MRG(a6,8)  MRG(a7,8)
#undef MRG

    if (ep == 0) {
        // z8 = e4m3( dinv[n] * sum(64*dinv_s*x_s) ) = e4m3(64*z)
        float di = d_dinv[g][n];
        float2 f0 = __half22float2(a0);
        float2 f1 = __half22float2(a1);
        float2 f2 = __half22float2(a2);
        float2 f3 = __half22float2(a3);
        float2 f4 = __half22float2(a4);
        float2 f5 = __half22float2(a5);
        float2 f6 = __half22float2(a6);
        float2 f7 = __half22float2(a7);
        unsigned short s0 = f32x2_to_e4m3x2(di * f0.x, di * f0.y);
        unsigned short s1 = f32x2_to_e4m3x2(di * f1.x, di * f1.y);
        unsigned short s2 = f32x2_to_e4m3x2(di * f2.x, di * f2.y);
        unsigned short s3 = f32x2_to_e4m3x2(di * f3.x, di * f3.y);
        unsigned short s4 = f32x2_to_e4m3x2(di * f4.x, di * f4.y);
        unsigned short s5 = f32x2_to_e4m3x2(di * f5.x, di * f5.y);
        unsigned short s6 = f32x2_to_e4m3x2(di * f6.x, di * f6.y);
        unsigned short s7 = f32x2_to_e4m3x2(di * f7.x, di * f7.y);
        uint4 o;
        o.x = (unsigned)s0 | ((unsigned)s1 << 16);
        o.y = (unsigned)s2 | ((unsigned)s3 << 16);
        o.z = (unsigned)s4 | ((unsigned)s5 << 16);
        o.w = (unsigned)s6 | ((unsigned)s7 << 16);
        *(uint4*)(d_z8[g] + n * DD + off * 16) = o;
    }
}

// ---------------- tensor-core GEMM: relu(z@W + b) column-summed ---------------
// z arrives as fp8 (64x scale), W as fp16 (1/64 scale) -> product is exact z*W.
#define SMB_ZS 0
#define SMB_WT (DD * ZPH * 2)                 // 34816
#define SMB_BS (SMB_WT + DD * ZPH * 2)        // 69632
#define SMB_RED (SMB_BS + DD * 4)             // 70144
#define SMB_TOT (SMB_RED + DD * 4)            // 70656

__global__ void __launch_bounds__(256, 2)
gemm_kernel(const float* __restrict__ b1, const float* __restrict__ b2,
            const float* __restrict__ b3) {
    extern __shared__ __align__(16) char smraw[];
    __half* zs = (__half*)(smraw + SMB_ZS);
    __half* Wt = (__half*)(smraw + SMB_WT);
    float*  bs = (float*)(smraw + SMB_BS);
    float*  red = (float*)(smraw + SMB_RED);

    int g = blockIdx.y;
    const float* b = (g == 0) ? b1 : ((g == 1) ? b2 : b3);
    int t = threadIdx.x;
    int row0 = blockIdx.x * 128;

    const uint4* wsrc = (const uint4*)d_wt[g];
    for (int i = t; i < 2048; i += 256) {
        int r = i >> 4, c = i & 15;
        *(uint4*)&Wt[r * ZPH + c * 8] = wsrc[r * 16 + c];
    }
    // load z tile: fp8 -> fp16 decode into smem
    const uint4* zsrc = (const uint4*)d_z8[g];     // row = 8 uint4 (128 fp8)
    uint4 zz; zz.x = zz.y = zz.z = zz.w = 0u;
    for (int i = t; i < 1024; i += 256) {
        int r = i >> 3, c = i & 7;
        int row = row0 + r;
        uint4 v = (row < NN) ? zsrc[row * 8 + c] : zz;
        __half2 h0 = e4m3x2_to_h2((unsigned short)(v.x));
        __half2 h1 = e4m3x2_to_h2((unsigned short)(v.x >> 16));
        __half2 h2 = e4m3x2_to_h2((unsigned short)(v.y));
        __half2 h3 = e4m3x2_to_h2((unsigned short)(v.y >> 16));
        __half2 h4 = e4m3x2_to_h2((unsigned short)(v.z));
        __half2 h5 = e4m3x2_to_h2((unsigned short)(v.z >> 16));
        __half2 h6 = e4m3x2_to_h2((unsigned short)(v.w));
        __half2 h7 = e4m3x2_to_h2((unsigned short)(v.w >> 16));
        uint4 o0, o1;
        o0.x = *(unsigned*)&h0; o0.y = *(unsigned*)&h1;
        o0.z = *(unsigned*)&h2; o0.w = *(unsigned*)&h3;
        o1.x = *(unsigned*)&h4; o1.y = *(unsigned*)&h5;
        o1.z = *(unsigned*)&h6; o1.w = *(unsigned*)&h7;
        uint4* zp = (uint4*)&zs[r * ZPH + c * 16];
        zp[0] = o0;
        zp[1] = o1;
    }
    if (t < DD) { bs[t] = b[t]; red[t] = 0.f; }
    __syncthreads();

    int lane = t & 31, w = t >> 5;
    int qr = lane >> 2;
    int q2 = (lane & 3) * 2;

    const __half* ar0 = &zs[(w * 16 + qr) * ZPH + q2];
    const __half* ar8 = ar0 + 8 * ZPH;

    float acc[16][4];
    #pragma unroll
    for (int j = 0; j < 16; j++)
        #pragma unroll
        for (int c = 0; c < 4; c++) acc[j][c] = 0.f;

    #pragma unroll
    for (int kc = 0; kc < 8; kc++) {
        int k = kc * 16;
        unsigned a0 = *(const unsigned*)(ar0 + k);
        unsigned a1 = *(const unsigned*)(ar8 + k);
        unsigned a2 = *(const unsigned*)(ar0 + k + 8);
        unsigned a3 = *(const unsigned*)(ar8 + k + 8);
        #pragma unroll
        for (int j = 0; j < 16; j++) {
            const __half* bp = &Wt[(j * 8 + qr) * ZPH + q2 + k];
            unsigned bf0 = *(const unsigned*)bp;
            unsigned bf1 = *(const unsigned*)(bp + 8);
            asm volatile(
                "mma.sync.aligned.m16n8k16.row.col.f32.f16.f16.f32 "
                "{%0,%1,%2,%3}, {%4,%5,%6,%7}, {%8,%9}, {%0,%1,%2,%3};"
                : "+f"(acc[j][0]), "+f"(acc[j][1]), "+f"(acc[j][2]), "+f"(acc[j][3])
                : "r"(a0), "r"(a1), "r"(a2), "r"(a3), "r"(bf0), "r"(bf1));
        }
    }

    int r0 = row0 + w * 16 + qr;
    int r8 = r0 + 8;
    bool v0 = r0 < NN, v8 = r8 < NN;
    #pragma unroll
    for (int j = 0; j < 16; j++) {
        int c0 = j * 8 + q2;
        float bb0 = bs[c0], bb1 = bs[c0 + 1];
        float s0 = (v0 ? fmaxf(acc[j][0] + bb0, 0.f) : 0.f)
                 + (v8 ? fmaxf(acc[j][2] + bb0, 0.f) : 0.f);
        float s1 = (v0 ? fmaxf(acc[j][1] + bb1, 0.f) : 0.f)
                 + (v8 ? fmaxf(acc[j][3] + bb1, 0.f) : 0.f);
        s0 += __shfl_down_sync(0xffffffffu, s0, 16);
        s1 += __shfl_down_sync(0xffffffffu, s1, 16);
        s0 += __shfl_down_sync(0xffffffffu, s0, 8);
        s1 += __shfl_down_sync(0xffffffffu, s1, 8);
        s0 += __shfl_down_sync(0xffffffffu, s0, 4);
        s1 += __shfl_down_sync(0xffffffffu, s1, 4);
        if (lane < 4) {
            atomicAdd(&red[c0], s0);
            atomicAdd(&red[c0 + 1], s1);
        }
    }
    __syncthreads();
    if (t < DD) atomicAdd(&d_gsum[g][t], red[t]);
}

// ---------------- head (also resets d_gsum for next call) ---------------------
__global__ void finalize_kernel(const float* __restrict__ a1w, const float* __restrict__ a1b,
                                const float* __restrict__ a2w, const float* __restrict__ a2b,
                                const float* __restrict__ a3w, const float* __restrict__ a3b,
                                const float* __restrict__ f1w, const float* __restrict__ f1b,
                                const float* __restrict__ f2w, const float* __restrict__ f2b,
                                float* __restrict__ out) {
    __shared__ float xin[3 * DD];
    __shared__ float h1[DD];
    __shared__ float h2[DD];
    __shared__ float aw[4];
    __shared__ float xa[DD];
    int t = threadIdx.x;
    xin[t]          = d_gsum[0][t];
    xin[DD + t]     = d_gsum[1][t];
    xin[2 * DD + t] = d_gsum[2][t];
    d_gsum[0][t] = 0.f;           // reset for next invocation (graph replay)
    d_gsum[1][t] = 0.f;
    d_gsum[2][t] = 0.f;
    __syncthreads();
    {
        float s = a1b[t];
        for (int j = 0; j < 3 * DD; j++) s += xin[j] * a1w[t * (3 * DD) + j];
        h1[t] = fmaxf(s, 0.f);
    }
    __syncthreads();
    {
        float s = a2b[t];
        for (int j = 0; j < DD; j++) s += h1[j] * a2w[t * DD + j];
        h2[t] = s;
    }
    __syncthreads();
    if (t < 3) {
        float s = a3b[t];
        for (int j = 0; j < DD; j++) s += fmaxf(h2[j], 0.f) * a3w[t * DD + j];
        aw[t] = s;
    }
    __syncthreads();
    if (t == 0) {
        float m = fmaxf(aw[0], fmaxf(aw[1], aw[2]));
        float e0 = expf(aw[0] - m), e1 = expf(aw[1] - m), e2 = expf(aw[2] - m);
        float S = e0 + e1 + e2;
        aw[0] = e0 / S; aw[1] = e1 / S; aw[2] = e2 / S;
    }
    __syncthreads();
    xa[t] = aw[0] * xin[t] + aw[1] * xin[DD + t] + aw[2] * xin[2 * DD + t];
    __syncthreads();
    float sg = f1b[t], sb = f2b[t];
    for (int j = 0; j < DD; j++) {
        float v = xa[j];
        sg += v * f1w[t * DD + j];
        sb += v * f2w[t * DD + j];
    }
    out[t]      = tanhf(sg);
    out[DD + t] = tanhf(sb);
}

// ---------------- launch ------------------------------------------------------
extern "C" void kernel_launch(void* const* d_in, const int* in_sizes, int n_in,
                              void* d_out, int out_size) {
    const float* x1 = (const float*)d_in[0];
    const float* x2 = (const float*)d_in[1];
    const float* x3 = (const float*)d_in[2];
    const int* e1 = (const int*)d_in[3];
    const int* e2 = (const int*)d_in[4];
    const int* e3 = (const int*)d_in[5];
    const float* W1 = (const float*)d_in[6];  const float* b1 = (const float*)d_in[7];
    const float* W2 = (const float*)d_in[8];  const float* b2 = (const float*)d_in[9];
    const float* W3 = (const float*)d_in[10]; const float* b3 = (const float*)d_in[11];
    const float* a1w = (const float*)d_in[12]; const float* a1b = (const float*)d_in[13];
    const float* a2w = (const float*)d_in[14]; const float* a2b = (const float*)d_in[15];
    const float* a3w = (const float*)d_in[16]; const float* a3b = (const float*)d_in[17];
    const float* f1w = (const float*)d_in[18]; const float* f1b = (const float*)d_in[19];
    const float* f2w = (const float*)d_in[20]; const float* f2b = (const float*)d_in[21];
    float* out = (float*)d_out;

    static bool attr_set = false;
    if (!attr_set) {
        cudaFuncSetAttribute(gemm_kernel, cudaFuncAttributeMaxDynamicSharedMemorySize,
                             SMB_TOT);
        attr_set = true;
    }

    hist_kernel<<<dim3(256, NG), 256>>>(e1, e2, e3);
    scan_kernel<<<dim3(NSCAN, NG), 256>>>();
    fill_convert_kernel<<<dim3(1076, NG), 256>>>(e1, e2, e3, x1, x2, x3, W1, W2, W3);
    gather_kernel<<<dim3((NN + 7) / 8, NG), 256>>>();
    gemm_kernel<<<dim3(NT128, NG), 256, SMB_TOT>>>(b1, b2, b3);
    finalize_kernel<<<1, DD>>>(a1w, a1b, a2w, a2b, a3w, a3b, f1w, f1b, f2w, f2b, out);
}

// round 17
// speedup vs baseline: 2.3380x; 1.0231x over previous
#include <cuda_runtime.h>
#include <cuda_fp16.h>
#include <math.h>

#define NN 50000
#define NE 800000
#define DD 128
#define NG 3
#define NSCAN 13
#define NT128 ((NN + 127) / 128)   // 391
#define ZPH 136                    // padded row pitch in halves

// ---------------- scratch ----------------------------------------------------
__device__ int           d_deg[NG][NN];       // zeroed statically; reset by fill_convert sec4
__device__ int           d_start[NG][NN + 1];
__device__ int           d_cursor[NG][NN];
__device__ int           d_srcs[NG][NE];
__device__ float         d_dinv[NG][NN];
__device__ unsigned char d_y8[NG][NN * DD];   // fp8 e4m3 of 64*dinv[n]*x[n]
__device__ unsigned char d_z8[NG][NN * DD];   // fp8 e4m3 of 64*z (aggregated)
__device__ __half        d_wt[NG][DD * DD];   // (W/64) transposed fp16
__device__ float         d_gsum[NG][DD];      // zeroed statically; reset by finalize

// ---------------- PDL helpers -------------------------------------------------
__device__ __forceinline__ void pdl_wait() {
    asm volatile("griddepcontrol.wait;" ::: "memory");
}
__device__ __forceinline__ void pdl_trigger() {
    asm volatile("griddepcontrol.launch_dependents;" ::: "memory");
}

// ---------------- fp8 helpers -------------------------------------------------
__device__ __forceinline__ unsigned short f32x2_to_e4m3x2(float lo, float hi) {
    unsigned short r;
    asm("cvt.rn.satfinite.e4m3x2.f32 %0, %1, %2;" : "=h"(r) : "f"(hi), "f"(lo));
    return r;
}
__device__ __forceinline__ __half2 e4m3x2_to_h2(unsigned short u) {
    unsigned r;
    asm("cvt.rn.f16x2.e4m3x2 %0, %1;" : "=r"(r) : "h"(u));
    return *(__half2*)&r;
}

// ---------------- hist --------------------------------------------------------
__global__ void hist_kernel(const int* __restrict__ e1,
                            const int* __restrict__ e2,
                            const int* __restrict__ e3) {
    int g = blockIdx.y;
    const int* ei = (g == 0) ? e1 : ((g == 1) ? e2 : e3);
    const int4* dst4 = (const int4*)(ei + NE);
    int stride = gridDim.x * blockDim.x;
    // deg was reset by previous invocation's fill_convert (or static zero init);
    // the harness serializes invocations, so no wait needed on inputs.
    for (int i = blockIdx.x * blockDim.x + threadIdx.x; i < NE / 4; i += stride) {
        int4 d = dst4[i];
        atomicAdd(&d_deg[g][d.x], 1);
        atomicAdd(&d_deg[g][d.y], 1);
        atomicAdd(&d_deg[g][d.z], 1);
        atomicAdd(&d_deg[g][d.w], 1);
    }
    pdl_trigger();
}

// ---------------- single-pass scan: grid (NSCAN, NG) x 256 --------------------
__global__ void scan_kernel() {
    int g = blockIdx.y;
    int bx = blockIdx.x;
    int t = threadIdx.x;
    int lane = t & 31, wid = t >> 5;

    pdl_wait();                      // need complete histogram
    const int4* deg4 = (const int4*)d_deg[g];

    // prefix base = sum of deg[0 .. bx*4096)
    int pre = 0;
    int nPrev4 = bx * 1024;
    for (int i = t; i < nPrev4; i += 256) {
        int4 v = deg4[i];
        pre += v.x + v.y + v.z + v.w;
    }
    #pragma unroll
    for (int o = 16; o; o >>= 1) pre += __shfl_down_sync(0xffffffffu, pre, o);
    __shared__ int red8[8];
    __shared__ int bofs;
    if (lane == 0) red8[wid] = pre;
    __syncthreads();
    if (t == 0) {
        int s = 0;
        #pragma unroll
        for (int w = 0; w < 8; w++) s += red8[w];
        bofs = s;
    }

    // local chunk scan
    int base = bx * 4096 + t * 16;
    int v[16];
    int s = 0;
    #pragma unroll
    for (int i = 0; i < 16; i++) {
        int idx = base + i;
        v[i] = (idx < NN) ? d_deg[g][idx] : 0;
        s += v[i];
    }
    int incl = s;
    #pragma unroll
    for (int o = 1; o < 32; o <<= 1) {
        int y = __shfl_up_sync(0xffffffffu, incl, o);
        if (lane >= o) incl += y;
    }
    __shared__ int ws[8];
    if (lane == 31) ws[wid] = incl;
    __syncthreads();
    if (t == 0) {
        int run = 0;
        #pragma unroll
        for (int w = 0; w < 8; w++) { int tmp = ws[w]; ws[w] = run; run += tmp; }
    }
    __syncthreads();
    int run = bofs + ws[wid] + (incl - s);
    #pragma unroll
    for (int i = 0; i < 16; i++) {
        int idx = base + i;
        if (idx < NN) {
            d_start[g][idx]  = run;
            d_cursor[g][idx] = run;
            d_dinv[g][idx]   = rsqrtf((float)(v[i] + 1));
            run += v[i];
        }
    }
    if (t == 0 && bx == 0) d_start[g][NN] = NE;
    pdl_trigger();
}

// ---------------- merged fill + convert + W transpose + deg reset -------------
// grid (1076, NG): [0,512) fill, [512,1024) convert, [1024,1028) W, [1028,1076) deg reset
__global__ void fill_convert_kernel(const int* __restrict__ e1,
                                    const int* __restrict__ e2,
                                    const int* __restrict__ e3,
                                    const float* __restrict__ x1,
                                    const float* __restrict__ x2,
                                    const float* __restrict__ x3,
                                    const float* __restrict__ W1,
                                    const float* __restrict__ W2,
                                    const float* __restrict__ W3) {
    int g = blockIdx.y;
    int t = threadIdx.x;
    int bx = blockIdx.x;

    if (bx >= 1024 && bx < 1028) {
        // ---- W transpose -> fp16/64: reads ONLY kernel inputs, no wait ----
        const float* W = (g == 0) ? W1 : ((g == 1) ? W2 : W3);
        __half* wt = d_wt[g];
        int gid = (bx - 1024) * 256 + t;   // 0..1023
        int j = gid >> 3;
        int k0 = (gid & 7) * 16;
        #pragma unroll
        for (int kk = 0; kk < 16; kk++)
            wt[j * DD + k0 + kk] = __float2half(W[(k0 + kk) * DD + j] * (1.f / 64.f));
        pdl_trigger();
        return;
    }

    pdl_wait();                      // need scan outputs (cursor/dinv) and scan's deg reads done
    if (bx < 512) {
        // ---- fill CSR ----
        const int* ei = (g == 0) ? e1 : ((g == 1) ? e2 : e3);
        const int4* src4 = (const int4*)ei;
        const int4* dst4 = (const int4*)(ei + NE);
        int stride = 512 * 256;
        int* srcs = d_srcs[g];
        int* cur  = d_cursor[g];
        for (int i = bx * 256 + t; i < NE / 4; i += stride) {
            int4 sv = src4[i];
            int4 dv = dst4[i];
            srcs[atomicAdd(&cur[dv.x], 1)] = sv.x;
            srcs[atomicAdd(&cur[dv.y], 1)] = sv.y;
            srcs[atomicAdd(&cur[dv.z], 1)] = sv.z;
            srcs[atomicAdd(&cur[dv.w], 1)] = sv.w;
        }
    } else if (bx < 1024) {
        // ---- convert x -> fp8 y8 ----
        const float4* x4 = (const float4*)((g == 0) ? x1 : ((g == 1) ? x2 : x3));
        const float* dinv = d_dinv[g];
        uint4* y4 = (uint4*)d_y8[g];
        int stride = 512 * 256;
        for (int i = (bx - 512) * 256 + t; i < NN * 8; i += stride) {
            int n = i >> 3;
            int c = i & 7;
            float sc = 64.f * dinv[n];
            const float4* xp = x4 + n * 32 + c * 4;
            float4 v0 = xp[0], v1 = xp[1], v2 = xp[2], v3 = xp[3];
            unsigned short s0 = f32x2_to_e4m3x2(sc * v0.x, sc * v0.y);
            unsigned short s1 = f32x2_to_e4m3x2(sc * v0.z, sc * v0.w);
            unsigned short s2 = f32x2_to_e4m3x2(sc * v1.x, sc * v1.y);
            unsigned short s3 = f32x2_to_e4m3x2(sc * v1.z, sc * v1.w);
            unsigned short s4 = f32x2_to_e4m3x2(sc * v2.x, sc * v2.y);
            unsigned short s5 = f32x2_to_e4m3x2(sc * v2.z, sc * v2.w);
            unsigned short s6 = f32x2_to_e4m3x2(sc * v3.x, sc * v3.y);
            unsigned short s7 = f32x2_to_e4m3x2(sc * v3.z, sc * v3.w);
            uint4 o;
            o.x = (unsigned)s0 | ((unsigned)s1 << 16);
            o.y = (unsigned)s2 | ((unsigned)s3 << 16);
            o.z = (unsigned)s4 | ((unsigned)s5 << 16);
            o.w = (unsigned)s6 | ((unsigned)s7 << 16);
            y4[i] = o;
        }
    } else {
        // ---- reset deg for next invocation (scan has finished reading it) ----
        int4* deg4 = (int4*)d_deg[g];
        int4 z4 = make_int4(0, 0, 0, 0);
        int stride = 48 * 256;
        for (int i = (bx - 1028) * 256 + t; i < NN / 4; i += stride) deg4[i] = z4;
    }
    pdl_trigger();
}

// ---------------- gather (fp8 reads, fp16 accum, fp8 z out) -------------------
__global__ void gather_kernel() {
    int g = blockIdx.y;
    int warp = (blockIdx.x * blockDim.x + threadIdx.x) >> 5;
    int lane = threadIdx.x & 31;
    int n = warp;
    int ep  = lane >> 3;        // edge slot 0..3
    int off = lane & 7;         // 16B chunk within row

    pdl_wait();                 // need srcs + y8 from fill_convert
    if (warp >= NN) { pdl_trigger(); return; }
    const uint4* ybase = (const uint4*)d_y8[g];   // row = 8 uint4
    int s = d_start[g][n];
    int e = d_start[g][n + 1];
    const int* srcs = d_srcs[g];

    __half2 zero2 = __float2half2_rn(0.f);
    __half2 a0 = zero2, a1 = zero2, a2 = zero2, a3 = zero2;
    __half2 a4 = zero2, a5 = zero2, a6 = zero2, a7 = zero2;

#define ACC16(vv) {                                                   \
        a0 = __hadd2(a0, e4m3x2_to_h2((unsigned short)((vv).x)));     \
        a1 = __hadd2(a1, e4m3x2_to_h2((unsigned short)((vv).x >> 16)));\
        a2 = __hadd2(a2, e4m3x2_to_h2((unsigned short)((vv).y)));     \
        a3 = __hadd2(a3, e4m3x2_to_h2((unsigned short)((vv).y >> 16)));\
        a4 = __hadd2(a4, e4m3x2_to_h2((unsigned short)((vv).z)));     \
        a5 = __hadd2(a5, e4m3x2_to_h2((unsigned short)((vv).z >> 16)));\
        a6 = __hadd2(a6, e4m3x2_to_h2((unsigned short)((vv).w)));     \
        a7 = __hadd2(a7, e4m3x2_to_h2((unsigned short)((vv).w >> 16)));}

    int i = s;
    for (; i + 8 <= e; i += 8) {
        int s0 = srcs[i + ep];
        int s1 = srcs[i + 4 + ep];
        uint4 v0 = ybase[s0 * 8 + off];
        uint4 v1 = ybase[s1 * 8 + off];
        ACC16(v0); ACC16(v1);
    }
    for (; i + 4 <= e; i += 4) {
        int s0 = srcs[i + ep];
        uint4 v0 = ybase[s0 * 8 + off];
        ACC16(v0);
    }
    {
        int r = e - i;
        int sv = (ep < r) ? srcs[i + ep] : ((ep == r) ? n : -1);
        if (sv >= 0) {
            uint4 v0 = ybase[sv * 8 + off];
            ACC16(v0);
        }
    }
#undef ACC16

#define MRG(aa, d) {                                                     \
        unsigned uu = __shfl_down_sync(0xffffffffu, *(unsigned*)&(aa), d);\
        (aa) = __hadd2((aa), *(__half2*)&uu);                             }
    MRG(a0,16) MRG(a1,16) MRG(a2,16) MRG(a3,16)
    MRG(a4,16) MRG(a5,16) MRG(a6,16) MRG(a7,16)
    MRG(a0,8)  MRG(a1,8)  MRG(a2,8)  MRG(a3,8)
    MRG(a4,8)  MRG(a5,8)  MRG(a6,8)  MRG(a7,8)
#undef MRG

    if (ep == 0) {
        float di = d_dinv[g][n];
        float2 f0 = __half22float2(a0);
        float2 f1 = __half22float2(a1);
        float2 f2 = __half22float2(a2);
        float2 f3 = __half22float2(a3);
        float2 f4 = __half22float2(a4);
        float2 f5 = __half22float2(a5);
        float2 f6 = __half22float2(a6);
        float2 f7 = __half22float2(a7);
        unsigned short s0 = f32x2_to_e4m3x2(di * f0.x, di * f0.y);
        unsigned short s1 = f32x2_to_e4m3x2(di * f1.x, di * f1.y);
        unsigned short s2 = f32x2_to_e4m3x2(di * f2.x, di * f2.y);
        unsigned short s3 = f32x2_to_e4m3x2(di * f3.x, di * f3.y);
        unsigned short s4 = f32x2_to_e4m3x2(di * f4.x, di * f4.y);
        unsigned short s5 = f32x2_to_e4m3x2(di * f5.x, di * f5.y);
        unsigned short s6 = f32x2_to_e4m3x2(di * f6.x, di * f6.y);
        unsigned short s7 = f32x2_to_e4m3x2(di * f7.x, di * f7.y);
        uint4 o;
        o.x = (unsigned)s0 | ((unsigned)s1 << 16);
        o.y = (unsigned)s2 | ((unsigned)s3 << 16);
        o.z = (unsigned)s4 | ((unsigned)s5 << 16);
        o.w = (unsigned)s6 | ((unsigned)s7 << 16);
        *(uint4*)(d_z8[g] + n * DD + off * 16) = o;
    }
    pdl_trigger();
}

// ---------------- tensor-core GEMM: relu(z@W + b) column-summed ---------------
#define SMB_ZS 0
#define SMB_WT (DD * ZPH * 2)                 // 34816
#define SMB_BS (SMB_WT + DD * ZPH * 2)        // 69632
#define SMB_RED (SMB_BS + DD * 4)             // 70144
#define SMB_TOT (SMB_RED + DD * 4)            // 70656

__global__ void __launch_bounds__(256, 2)
gemm_kernel(const float* __restrict__ b1, const float* __restrict__ b2,
            const float* __restrict__ b3) {
    extern __shared__ __align__(16) char smraw[];
    __half* zs = (__half*)(smraw + SMB_ZS);
    __half* Wt = (__half*)(smraw + SMB_WT);
    float*  bs = (float*)(smraw + SMB_BS);
    float*  red = (float*)(smraw + SMB_RED);

    int g = blockIdx.y;
    const float* b = (g == 0) ? b1 : ((g == 1) ? b2 : b3);
    int t = threadIdx.x;
    int row0 = blockIdx.x * 128;

    // ---- PROLOGUE (independent of gather): Wt smem load + bias + red init ----
    const uint4* wsrc = (const uint4*)d_wt[g];    // written 2 launches ago
    for (int i = t; i < 2048; i += 256) {
        int r = i >> 4, c = i & 15;
        *(uint4*)&Wt[r * ZPH + c * 8] = wsrc[r * 16 + c];
    }
    if (t < DD) { bs[t] = b[t]; red[t] = 0.f; }

    pdl_wait();                 // need z8 from gather

    // load z tile: fp8 -> fp16 decode into smem
    const uint4* zsrc = (const uint4*)d_z8[g];     // row = 8 uint4 (128 fp8)
    uint4 zz; zz.x = zz.y = zz.z = zz.w = 0u;
    for (int i = t; i < 1024; i += 256) {
        int r = i >> 3, c = i & 7;
        int row = row0 + r;
        uint4 v = (row < NN) ? zsrc[row * 8 + c] : zz;
        __half2 h0 = e4m3x2_to_h2((unsigned short)(v.x));
        __half2 h1 = e4m3x2_to_h2((unsigned short)(v.x >> 16));
        __half2 h2 = e4m3x2_to_h2((unsigned short)(v.y));
        __half2 h3 = e4m3x2_to_h2((unsigned short)(v.y >> 16));
        __half2 h4 = e4m3x2_to_h2((unsigned short)(v.z));
        __half2 h5 = e4m3x2_to_h2((unsigned short)(v.z >> 16));
        __half2 h6 = e4m3x2_to_h2((unsigned short)(v.w));
        __half2 h7 = e4m3x2_to_h2((unsigned short)(v.w >> 16));
        uint4 o0, o1;
        o0.x = *(unsigned*)&h0; o0.y = *(unsigned*)&h1;
        o0.z = *(unsigned*)&h2; o0.w = *(unsigned*)&h3;
        o1.x = *(unsigned*)&h4; o1.y = *(unsigned*)&h5;
        o1.z = *(unsigned*)&h6; o1.w = *(unsigned*)&h7;
        uint4* zp = (uint4*)&zs[r * ZPH + c * 16];
        zp[0] = o0;
        zp[1] = o1;
    }
    __syncthreads();

    int lane = t & 31, w = t >> 5;
    int qr = lane >> 2;
    int q2 = (lane & 3) * 2;

    const __half* ar0 = &zs[(w * 16 + qr) * ZPH + q2];
    const __half* ar8 = ar0 + 8 * ZPH;

    float acc[16][4];
    #pragma unroll
    for (int j = 0; j < 16; j++)
        #pragma unroll
        for (int c = 0; c < 4; c++) acc[j][c] = 0.f;

    #pragma unroll
    for (int kc = 0; kc < 8; kc++) {
        int k = kc * 16;
        unsigned a0 = *(const unsigned*)(ar0 + k);
        unsigned a1 = *(const unsigned*)(ar8 + k);
        unsigned a2 = *(const unsigned*)(ar0 + k + 8);
        unsigned a3 = *(const unsigned*)(ar8 + k + 8);
        #pragma unroll
        for (int j = 0; j < 16; j++) {
            const __half* bp = &Wt[(j * 8 + qr) * ZPH + q2 + k];
            unsigned bf0 = *(const unsigned*)bp;
            unsigned bf1 = *(const unsigned*)(bp + 8);
            asm volatile(
                "mma.sync.aligned.m16n8k16.row.col.f32.f16.f16.f32 "
                "{%0,%1,%2,%3}, {%4,%5,%6,%7}, {%8,%9}, {%0,%1,%2,%3};"
                : "+f"(acc[j][0]), "+f"(acc[j][1]), "+f"(acc[j][2]), "+f"(acc[j][3])
                : "r"(a0), "r"(a1), "r"(a2), "r"(a3), "r"(bf0), "r"(bf1));
        }
    }

    int r0 = row0 + w * 16 + qr;
    int r8 = r0 + 8;
    bool v0 = r0 < NN, v8 = r8 < NN;
    #pragma unroll
    for (int j = 0; j < 16; j++) {
        int c0 = j * 8 + q2;
        float bb0 = bs[c0], bb1 = bs[c0 + 1];
        float s0 = (v0 ? fmaxf(acc[j][0] + bb0, 0.f) : 0.f)
                 + (v8 ? fmaxf(acc[j][2] + bb0, 0.f) : 0.f);
        float s1 = (v0 ? fmaxf(acc[j][1] + bb1, 0.f) : 0.f)
                 + (v8 ? fmaxf(acc[j][3] + bb1, 0.f) : 0.f);
        s0 += __shfl_down_sync(0xffffffffu, s0, 16);
        s1 += __shfl_down_sync(0xffffffffu, s1, 16);
        s0 += __shfl_down_sync(0xffffffffu, s0, 8);
        s1 += __shfl_down_sync(0xffffffffu, s1, 8);
        s0 += __shfl_down_sync(0xffffffffu, s0, 4);
        s1 += __shfl_down_sync(0xffffffffu, s1, 4);
        if (lane < 4) {
            atomicAdd(&red[c0], s0);
            atomicAdd(&red[c0 + 1], s1);
        }
    }
    __syncthreads();
    if (t < DD) atomicAdd(&d_gsum[g][t], red[t]);
    pdl_trigger();
}

// ---------------- head (also resets d_gsum for next call) ---------------------
__global__ void finalize_kernel(const float* __restrict__ a1w, const float* __restrict__ a1b,
                                const float* __restrict__ a2w, const float* __restrict__ a2b,
                                const float* __restrict__ a3w, const float* __restrict__ a3b,
                                const float* __restrict__ f1w, const float* __restrict__ f1b,
                                const float* __restrict__ f2w, const float* __restrict__ f2b,
                                float* __restrict__ out) {
    __shared__ float xin[3 * DD];
    __shared__ float h1[DD];
    __shared__ float h2[DD];
    __shared__ float aw[4];
    __shared__ float xa[DD];
    int t = threadIdx.x;
    pdl_wait();                 // need gsum from gemm
    xin[t]          = d_gsum[0][t];
    xin[DD + t]     = d_gsum[1][t];
    xin[2 * DD + t] = d_gsum[2][t];
    d_gsum[0][t] = 0.f;           // reset for next invocation (graph replay)
    d_gsum[1][t] = 0.f;
    d_gsum[2][t] = 0.f;
    __syncthreads();
    {
        float s = a1b[t];
        for (int j = 0; j < 3 * DD; j++) s += xin[j] * a1w[t * (3 * DD) + j];
        h1[t] = fmaxf(s, 0.f);
    }
    __syncthreads();
    {
        float s = a2b[t];
        for (int j = 0; j < DD; j++) s += h1[j] * a2w[t * DD + j];
        h2[t] = s;
    }
    __syncthreads();
    if (t < 3) {
        float s = a3b[t];
        for (int j = 0; j < DD; j++) s += fmaxf(h2[j], 0.f) * a3w[t * DD + j];
        aw[t] = s;
    }
    __syncthreads();
    if (t == 0) {
        float m = fmaxf(aw[0], fmaxf(aw[1], aw[2]));
        float e0 = expf(aw[0] - m), e1 = expf(aw[1] - m), e2 = expf(aw[2] - m);
        float S = e0 + e1 + e2;
        aw[0] = e0 / S; aw[1] = e1 / S; aw[2] = e2 / S;
    }
    __syncthreads();
    xa[t] = aw[0] * xin[t] + aw[1] * xin[DD + t] + aw[2] * xin[2 * DD + t];
    __syncthreads();
    float sg = f1b[t], sb = f2b[t];
    for (int j = 0; j < DD; j++) {
        float v = xa[j];
        sg += v * f1w[t * DD + j];
        sb += v * f2w[t * DD + j];
    }
    out[t]      = tanhf(sg);
    out[DD + t] = tanhf(sb);
}

// ---------------- launch ------------------------------------------------------
extern "C" void kernel_launch(void* const* d_in, const int* in_sizes, int n_in,
                              void* d_out, int out_size) {
    const float* x1 = (const float*)d_in[0];
    const float* x2 = (const float*)d_in[1];
    const float* x3 = (const float*)d_in[2];
    const int* e1 = (const int*)d_in[3];
    const int* e2 = (const int*)d_in[4];
    const int* e3 = (const int*)d_in[5];
    const float* W1 = (const float*)d_in[6];  const float* b1 = (const float*)d_in[7];
    const float* W2 = (const float*)d_in[8];  const float* b2 = (const float*)d_in[9];
    const float* W3 = (const float*)d_in[10]; const float* b3 = (const float*)d_in[11];
    const float* a1w = (const float*)d_in[12]; const float* a1b = (const float*)d_in[13];
    const float* a2w = (const float*)d_in[14]; const float* a2b = (const float*)d_in[15];
    const float* a3w = (const float*)d_in[16]; const float* a3b = (const float*)d_in[17];
    const float* f1w = (const float*)d_in[18]; const float* f1b = (const float*)d_in[19];
    const float* f2w = (const float*)d_in[20]; const float* f2b = (const float*)d_in[21];
    float* out = (float*)d_out;

    static bool attr_set = false;
    if (!attr_set) {
        cudaFuncSetAttribute(gemm_kernel, cudaFuncAttributeMaxDynamicSharedMemorySize,
                             SMB_TOT);
        attr_set = true;
    }

    cudaLaunchAttribute pdl_attr[1];
    pdl_attr[0].id = cudaLaunchAttributeProgrammaticStreamSerialization;
    pdl_attr[0].val.programmaticStreamSerializationAllowed = 1;

    // hist: normal launch
    hist_kernel<<<dim3(256, NG), 256>>>(e1, e2, e3);

    // scan: PDL
    {
        cudaLaunchConfig_t cfg = {};
        cfg.gridDim = dim3(NSCAN, NG);
        cfg.blockDim = dim3(256);
        cfg.attrs = pdl_attr;
        cfg.numAttrs = 1;
        cudaLaunchKernelEx(&cfg, scan_kernel);
    }
    // fill_convert: PDL
    {
        cudaLaunchConfig_t cfg = {};
        cfg.gridDim = dim3(1076, NG);
        cfg.blockDim = dim3(256);
        cfg.attrs = pdl_attr;
        cfg.numAttrs = 1;
        cudaLaunchKernelEx(&cfg, fill_convert_kernel, e1, e2, e3, x1, x2, x3, W1, W2, W3);
    }
    // gather: PDL
    {
        cudaLaunchConfig_t cfg = {};
        cfg.gridDim = dim3((NN + 7) / 8, NG);
        cfg.blockDim = dim3(256);
        cfg.attrs = pdl_attr;
        cfg.numAttrs = 1;
        cudaLaunchKernelEx(&cfg, gather_kernel);
    }
    // gemm: PDL + dynamic smem
    {
        cudaLaunchConfig_t cfg = {};
        cfg.gridDim = dim3(NT128, NG);
        cfg.blockDim = dim3(256);
        cfg.dynamicSmemBytes = SMB_TOT;
        cfg.attrs = pdl_attr;
        cfg.numAttrs = 1;
        cudaLaunchKernelEx(&cfg, gemm_kernel, b1, b2, b3);
    }
    // finalize: PDL
    {
        cudaLaunchConfig_t cfg = {};
        cfg.gridDim = dim3(1);
        cfg.blockDim = dim3(DD);
        cfg.attrs = pdl_attr;
        cfg.numAttrs = 1;
        cudaLaunchKernelEx(&cfg, finalize_kernel, a1w, a1b, a2w, a2b, a3w, a3b,
                           f1w, f1b, f2w, f2b, out);
    }
}